// round 3
// baseline (speedup 1.0000x reference)
#include <cuda_runtime.h>

// DWT Haar loss: pred/target [32,3,512,512] fp32.
// Linear DWT -> operate on diff. Per 2x2 block (a,b,c,d) of diff:
//   contribution = |a+b+c+d| + |a+b-c-d| + |a-b+c-d| + |a-b-c+d|
// loss = 0.5 * sum / N_blocks.
//
// Viewed as 24576 row-pairs of 512 floats (128 float4 per row).
// One work item = one float4 column from row 2m + matching float4 from row
// 2m+1 (both tensors) = two 2x2 blocks. Unrolled 2x: 8 LDG.128 in flight.

static constexpr int TOTAL_QUADS = 24576 * 128;       // 3,145,728
static constexpr float SCALE = 0.5f / 6291456.0f;     // 0.5 / N_blocks

__device__ float    g_scratch = 0.0f;
__device__ unsigned g_ctr     = 0u;

__device__ __forceinline__ float haar_quad(const float4& p0, const float4& p1,
                                           const float4& t0, const float4& t1)
{
    float acc;
    {
        float a = p0.x - t0.x, b = p0.y - t0.y;
        float c = p1.x - t1.x, d = p1.y - t1.y;
        float apb = a + b, amb = a - b, cpd = c + d, cmd = c - d;
        acc = fabsf(apb + cpd) + fabsf(apb - cpd)
            + fabsf(amb + cmd) + fabsf(amb - cmd);
    }
    {
        float a = p0.z - t0.z, b = p0.w - t0.w;
        float c = p1.z - t1.z, d = p1.w - t1.w;
        float apb = a + b, amb = a - b, cpd = c + d, cmd = c - d;
        acc += fabsf(apb + cpd) + fabsf(apb - cpd)
             + fabsf(amb + cmd) + fabsf(amb - cmd);
    }
    return acc;
}

__global__ void __launch_bounds__(256) dwt_loss_kernel(
    const float4* __restrict__ pred,
    const float4* __restrict__ tgt,
    float* __restrict__ out)
{
    const int stride = gridDim.x * blockDim.x;
    float acc = 0.0f;

    int i = blockIdx.x * blockDim.x + threadIdx.x;
    // Unrolled by 2: issue all 8 loads before consuming.
    for (; i + stride < TOTAL_QUADS; i += 2 * stride) {
        const int j = i + stride;
        const int mi = i >> 7, qi = i & 127;
        const int mj = j >> 7, qj = j & 127;
        const int bi0 = mi * 256 + qi, bi1 = bi0 + 128;
        const int bj0 = mj * 256 + qj, bj1 = bj0 + 128;

        float4 pi0 = pred[bi0];
        float4 pi1 = pred[bi1];
        float4 pj0 = pred[bj0];
        float4 pj1 = pred[bj1];
        float4 ti0 = tgt[bi0];
        float4 ti1 = tgt[bi1];
        float4 tj0 = tgt[bj0];
        float4 tj1 = tgt[bj1];

        acc += haar_quad(pi0, pi1, ti0, ti1);
        acc += haar_quad(pj0, pj1, tj0, tj1);
    }
    if (i < TOTAL_QUADS) {
        const int m = i >> 7, q = i & 127;
        const int b0 = m * 256 + q, b1 = b0 + 128;
        float4 p0 = pred[b0];
        float4 p1 = pred[b1];
        float4 t0 = tgt[b0];
        float4 t1 = tgt[b1];
        acc += haar_quad(p0, p1, t0, t1);
    }

    // Warp reduction
    #pragma unroll
    for (int o = 16; o > 0; o >>= 1)
        acc += __shfl_xor_sync(0xffffffffu, acc, o);

    __shared__ float warp_sums[8];
    if ((threadIdx.x & 31) == 0)
        warp_sums[threadIdx.x >> 5] = acc;
    __syncthreads();

    if (threadIdx.x < 32) {
        float v = (threadIdx.x < 8) ? warp_sums[threadIdx.x] : 0.0f;
        #pragma unroll
        for (int o = 4; o > 0; o >>= 1)
            v += __shfl_xor_sync(0xffffffffu, v, o);

        if (threadIdx.x == 0) {
            atomicAdd(&g_scratch, v);
            __threadfence();
            unsigned old = atomicAdd(&g_ctr, 1u);
            if (old == gridDim.x - 1) {
                // Last CTA: finalize and reset state for next graph replay.
                float total = atomicAdd(&g_scratch, 0.0f);
                out[0] = total * SCALE;
                atomicExch(&g_scratch, 0.0f);
                atomicExch(&g_ctr, 0u);
            }
        }
    }
}

extern "C" void kernel_launch(void* const* d_in, const int* in_sizes, int n_in,
                              void* d_out, int out_size) {
    const float4* pred = (const float4*)d_in[0];
    const float4* tgt  = (const float4*)d_in[1];
    float* out = (float*)d_out;

    // 2 full waves: 148 SMs * 8 CTAs (256 thr, 32 regs) * 2.
    dwt_loss_kernel<<<2368, 256>>>(pred, tgt, out);
}